// round 16
// baseline (speedup 1.0000x reference)
#include <cuda_runtime.h>

// Shapes fixed by setup_inputs
#define RADIUS 3
constexpr int N_ = 2, C_ = 64, S_ = 4, H_ = 64, W_ = 44;
constexpr int P_  = H_ * W_;
constexpr int SP_ = S_ * P_;                  // 11264 (channel stride)

constexpr int TILE_Y  = 4;
constexpr int ROWS_SM = 10;
constexpr int ROWF    = 100;   // floats per (cpair,row) = 25 float4 (ODD -> bank tiling)
constexpr int NTHREADS = 672;  // 7 tap-row groups x 96 (21 warps)
constexpr int NPIX    = 176;
constexpr int NUNIT   = 4928;  // 3520 f1 + 1408 f0 staging units

constexpr int F1_FL = 32 * ROWS_SM * ROWF;    // 32000 floats
constexpr int F0_FL = 32 * TILE_Y * ROWF;     // 12800 floats
constexpr int SMEM_BYTES = (F1_FL + F0_FL + 7 * NPIX * 4) * 4;   // 198912

using ull = unsigned long long;

__device__ __forceinline__ void fma2(ull& d, ull a, ull b) {
    asm("fma.rn.f32x2 %0, %1, %2, %0;" : "+l"(d) : "l"(a), "l"(b));
}
__device__ __forceinline__ void upk(float& lo, float& hi, ull v) {
    asm("mov.b64 {%0, %1}, %2;" : "=f"(lo), "=f"(hi) : "l"(v));
}

__global__ __launch_bounds__(NTHREADS, 1)
void flow_kernel(const float* __restrict__ f0g, const float* __restrict__ f1g,
                 float* __restrict__ outg) {
    extern __shared__ float sm[];
    float* f1s = sm;                  // [32 cp][10 row][50 slot][2ch]; slot = gx+3
    float* f0s = sm + F1_FL;          // [32 cp][4 yl][50 slot][2ch]; slot = x
    float4* red4 = reinterpret_cast<float4*>(sm + F1_FL + F0_FL);   // [7][176]

    const int tid  = threadIdx.x;
    const int y0   = blockIdx.x * TILE_Y;
    const int b    = blockIdx.y;
    const int ni   = b >> 2;
    const int si   = b & 3;
    const int base1 = ((ni * C_) * S_ + si) * P_;

    // ======== staging pass 1: ALL 16 LDG.128 front-batched ==================
    // No zero-fill: stale halo/OOB taps are masked in stats and never read.
    {
        float4 va[8], vb[8];
        int    off2[8];
        bool   okst[8];
        #pragma unroll
        for (int it = 0; it < 8; ++it) {
            const int u  = tid + it * NTHREADS;      // < 5376
            const int us = (u < NUNIT) ? u : 0;      // clamp: safe addr, store masked
            const float* src;
            if (us < 3520) {                         // f1 unit: (cp, row, k)
                const int cp  = us / 110;
                const int rem = us - cp * 110;
                const int row = rem / 11;
                const int k   = rem - row * 11;
                const int gy  = y0 - RADIUS + row;
                const bool inb = ((unsigned)gy < (unsigned)H_);
                const int gyc = inb ? gy : 0;
                src = f1g + base1 + (2 * cp) * SP_ + gyc * W_ + 4 * k;
                off2[it] = ((cp * ROWS_SM + row) * ROWF) / 2 + (4 * k + 3);
                okst[it] = (u < NUNIT) && inb;
            } else {                                 // f0 unit: (cp, yl, k)
                const int t   = us - 3520;
                const int cp  = t / 44;
                const int rem = t - cp * 44;
                const int yl  = rem / 11;
                const int k   = rem - yl * 11;
                src = f0g + base1 + (2 * cp) * SP_ + (y0 + yl) * W_ + 4 * k;
                off2[it] = (F1_FL + (cp * TILE_Y + yl) * ROWF) / 2 + 4 * k;
                okst[it] = (u < NUNIT);
            }
            va[it] = *(const float4*)src;            // 16 independent LDGs -> MLP
            vb[it] = *(const float4*)(src + SP_);
        }
        // ======== staging pass 2: interleave + store ========================
        #pragma unroll
        for (int it = 0; it < 8; ++it) {
            if (okst[it]) {
                float2* d2 = (float2*)sm + off2[it];
                const float4 a = va[it], v = vb[it];
                d2[0] = make_float2(a.x, v.x);
                d2[1] = make_float2(a.y, v.y);
                d2[2] = make_float2(a.z, v.z);
                d2[3] = make_float2(a.w, v.w);
            }
        }
    }
    __syncthreads();

    // ======== main loop: 2 px x 7 taps x 32 ch-pairs, pipelined LDS =========
    // Group g (96 thr) = tap row dy = g-3. q = (s>>5)*8 + (l&7), yl = l>>3:
    // every 8-lane phase = fixed yl, 8 consecutive f4 -> conflict-free.
    const int g   = tid / 96;
    const int s   = tid - g * 96;
    const int l   = s & 31;
    const int q   = (s >> 5) * 8 + (l & 7);
    const int yl  = l >> 3;
    const bool active = (q < 22);

    ull accA[7], accB[7];                     // px0 = 2q, px1 = 2q+1
    #pragma unroll
    for (int d = 0; d < 7; ++d) { accA[d] = 0ull; accB[d] = 0ull; }

    if (active) {
        const ulonglong2* __restrict__ tap =
            (const ulonglong2*)f1s + (yl + g) * 25 + q;   // f4 q..q+3 = slots 2q..2q+7
        const ulonglong2* __restrict__ a2 =
            (const ulonglong2*)f0s + yl * 25 + q;

        // prefetch cp=0
        ulonglong2 nT0 = tap[0], nT1 = tap[1], nT2 = tap[2], nT3 = tap[3];
        ulonglong2 nA  = a2[0];

        #pragma unroll 4
        for (int cp = 0; cp < 32; ++cp) {
            const ulonglong2 T0 = nT0, T1 = nT1, T2 = nT2, T3 = nT3;
            const ulonglong2 A  = nA;
            if (cp < 31) {                    // prefetch cp+1 while FMAs run
                tap += 250;                   // 10 rows * 25 f4 per cpair
                a2  += 100;                   // 4 rows * 25 f4
                nT0 = tap[0]; nT1 = tap[1]; nT2 = tap[2]; nT3 = tap[3];
                nA  = a2[0];
            }
            const ull U[8] = {T0.x, T0.y, T1.x, T1.y, T2.x, T2.y, T3.x, T3.y};
            #pragma unroll
            for (int d = 0; d < 7; ++d) fma2(accA[d], A.x, U[d]);
            #pragma unroll
            for (int d = 0; d < 7; ++d) fma2(accB[d], A.y, U[d + 1]);
        }
    }

    // ======== stats: merge ch-halves, masked per-row softmax ================
    if (active) {
        const bool rowv = ((unsigned)(y0 + yl + g - RADIUS) < (unsigned)H_);
        #pragma unroll
        for (int p = 0; p < 2; ++p) {
            const int x = 2 * q + p;          // 0..43
            const ull* acc = p ? accB : accA;
            float a[7];
            #pragma unroll
            for (int d = 0; d < 7; ++d) {
                float lo, hi;
                upk(lo, hi, acc[d]);
                a[d] = lo + hi;
            }
            float m = -1e30f;
            #pragma unroll
            for (int d = 0; d < 7; ++d) {
                const bool v = rowv && ((unsigned)(x + d - RADIUS) < (unsigned)W_);
                if (v) m = fmaxf(m, a[d]);
            }
            float ss = 0.0f, fx = 0.0f;
            #pragma unroll
            for (int d = 0; d < 7; ++d) {
                const bool v = rowv && ((unsigned)(x + d - RADIUS) < (unsigned)W_);
                const float e = v ? __expf((a[d] - m) * 0.125f) : 0.0f;
                ss += e;
                fx += e * (float)(d - RADIUS);
            }
            red4[g * NPIX + yl * W_ + x] = make_float4(m, ss, fx, 0.0f);
        }
    }
    __syncthreads();

    // ======== combine 7 row-partials per pixel ==============================
    if (tid < NPIX) {
        const int xl = tid % W_;
        const int yr = tid / W_;

        float4 p[7];
        #pragma unroll
        for (int gg = 0; gg < 7; ++gg) p[gg] = red4[gg * NPIX + tid];

        float M = p[0].x;
        #pragma unroll
        for (int gg = 1; gg < 7; ++gg) M = fmaxf(M, p[gg].x);

        float S = 0.0f, FX = 0.0f, FY = 0.0f;
        #pragma unroll
        for (int gg = 0; gg < 7; ++gg) {
            const float wg = __expf((p[gg].x - M) * 0.125f);   // empty row -> 0
            S  += p[gg].y * wg;
            FX += p[gg].z * wg;
            FY += p[gg].y * wg * (float)(gg - RADIUS);
        }
        const float inv = 1.0f / S;
        const int ob = ((ni * 2) * S_ + si) * P_ + (y0 + yr) * W_ + xl;
        outg[ob]       = FX * inv;
        outg[ob + SP_] = FY * inv;
    }
}

extern "C" void kernel_launch(void* const* d_in, const int* in_sizes, int n_in,
                              void* d_out, int out_size) {
    const float* f0 = (const float*)d_in[0];
    const float* f1 = (const float*)d_in[1];
    float* out = (float*)d_out;

    cudaFuncSetAttribute(flow_kernel,
                         cudaFuncAttributeMaxDynamicSharedMemorySize, SMEM_BYTES);

    dim3 grid(H_ / TILE_Y, N_ * S_);
    flow_kernel<<<grid, NTHREADS, SMEM_BYTES>>>(f0, f1, out);
}